// round 2
// baseline (speedup 1.0000x reference)
#include <cuda_runtime.h>
#include <math.h>

// ---------------- problem constants ----------------
constexpr int B_  = 8;
constexpr int H_  = 28;
constexpr int W_  = 28;
constexpr int C_  = 1024;
constexpr int NH_ = 16;
constexpr int HD_ = 64;
constexpr int S_  = H_ * W_;        // 784
constexpr int M_  = B_ * S_;        // 6272 rows
constexpr int HID_ = 4096;
constexpr int BC_  = 512;
constexpr int G_   = B_ * NH_;      // 128 attention batches
constexpr float SCALE_ = 0.125f;    // 64^-0.5

// ---------------- workspace (__device__ globals; no allocation allowed) ---
__device__ float g_xn   [M_ * C_];          // 25.7 MB
__device__ float g_qkv  [M_ * 3 * C_];      // 77 MB
__device__ float g_q    [G_ * S_ * HD_];    // 25.7 MB
__device__ float g_kT   [G_ * HD_ * S_];    // 25.7 MB
__device__ float g_v    [G_ * S_ * HD_];    // 25.7 MB
__device__ float g_bh   [G_ * S_ * H_];     // 11.2 MB
__device__ float g_bw   [G_ * S_ * W_];     // 11.2 MB
__device__ float g_attn [(size_t)G_ * S_ * S_];  // 315 MB
__device__ float g_ao   [M_ * C_];          // attention out, [B,S,C]
__device__ float g_x1   [M_ * C_];
__device__ float g_mlp  [M_ * HID_];        // 103 MB
__device__ float g_x2   [M_ * C_];
__device__ float g_c1   [M_ * BC_];
__device__ float g_c1a  [M_ * BC_];
__device__ float g_c2   [M_ * BC_];
__device__ float g_c2a  [M_ * BC_];
__device__ float g_c3   [M_ * C_];

__device__ __forceinline__ float gelu_f(float x) {
    return 0.5f * x * (1.0f + erff(x * 0.7071067811865475f));
}

// ---------------- generic tiled SGEMM ----------------
// C[M,N] = alpha * A[M,K] @ B[K,N]  (+bias[n]) with epilogue:
//   EPI 0: plain   EPI 1: gelu   EPI 2: + res[gr*ldres+gc]
//   EPI 3: + bh[(g*M+gr)*28 + gc/28] + bw[(g*M+gr)*28 + gc%28]  (attn scores)
//   EPI 4: scatter to [B,S,C]: C[((g/16)*784+gr)*1024 + (g%16)*64 + gc]
template<int BM, int BN, int BK, int TM, int TN, int EPI>
__global__ void sgemm_k(const float* __restrict__ A, const float* __restrict__ Bm,
                        float* __restrict__ Cm,
                        int M, int N, int K, int lda, int ldb, int ldc,
                        long long sA, long long sB, long long sC,
                        const float* __restrict__ bias,
                        const float* __restrict__ res, int ldres,
                        float alpha,
                        const float* __restrict__ bh, const float* __restrict__ bw)
{
    constexpr int THREADS = (BM / TM) * (BN / TN);
    __shared__ float As[BK][BM];
    __shared__ float Bs[BK][BN];

    const int tid = threadIdx.x;
    const int bm = blockIdx.x * BM;
    const int bn = blockIdx.y * BN;
    const int g  = blockIdx.z;
    A  += (size_t)g * sA;
    Bm += (size_t)g * sB;
    if (EPI != 4) Cm += (size_t)g * sC;

    const int tc = (tid % (BN / TN)) * TN;
    const int tr = (tid / (BN / TN)) * TM;

    float acc[TM][TN];
    #pragma unroll
    for (int m = 0; m < TM; m++)
        #pragma unroll
        for (int n = 0; n < TN; n++) acc[m][n] = 0.f;

    for (int k0 = 0; k0 < K; k0 += BK) {
        for (int i = tid; i < BM * BK; i += THREADS) {
            int r = i / BK, c = i % BK;
            int gr = bm + r;
            As[c][r] = (gr < M) ? A[(size_t)gr * lda + (k0 + c)] : 0.f;
        }
        for (int i = tid; i < BK * BN; i += THREADS) {
            int r = i / BN, c = i % BN;
            int gc = bn + c;
            Bs[r][c] = (gc < N) ? Bm[(size_t)(k0 + r) * ldb + gc] : 0.f;
        }
        __syncthreads();
        #pragma unroll
        for (int kk = 0; kk < BK; kk++) {
            float av[TM], bv[TN];
            #pragma unroll
            for (int m = 0; m < TM; m++) av[m] = As[kk][tr + m];
            #pragma unroll
            for (int n = 0; n < TN; n++) bv[n] = Bs[kk][tc + n];
            #pragma unroll
            for (int m = 0; m < TM; m++)
                #pragma unroll
                for (int n = 0; n < TN; n++)
                    acc[m][n] = fmaf(av[m], bv[n], acc[m][n]);
        }
        __syncthreads();
    }

    #pragma unroll
    for (int m = 0; m < TM; m++) {
        int gr = bm + tr + m;
        if (gr >= M) continue;
        #pragma unroll
        for (int n = 0; n < TN; n++) {
            int gc = bn + tc + n;
            if (gc >= N) continue;
            float v = alpha * acc[m][n];
            if (bias) v += bias[gc];
            if (EPI == 1) v = gelu_f(v);
            else if (EPI == 2) v += res[(size_t)gr * ldres + gc];
            else if (EPI == 3) v += bh[((size_t)g * M + gr) * 28 + gc / 28]
                                  + bw[((size_t)g * M + gr) * 28 + gc % 28];
            if (EPI == 4)
                Cm[((size_t)(g >> 4) * 784 + gr) * 1024 + (g & 15) * 64 + gc] = v;
            else
                Cm[(size_t)gr * ldc + gc] = v;
        }
    }
}

// ---------------- 3x3 conv as implicit GEMM (512->512, pad 1) --------------
template<int BM, int BN, int BK, int TM, int TN>
__global__ void conv3x3_k(const float* __restrict__ In, const float* __restrict__ Wt,
                          float* __restrict__ Out)
{
    constexpr int THREADS = (BM / TM) * (BN / TN);
    constexpr int M = M_, N = BC_, K = 9 * BC_;   // 6272, 512, 4608
    __shared__ float As[BK][BM];
    __shared__ float Bs[BK][BN];

    const int tid = threadIdx.x;
    const int bm = blockIdx.x * BM;
    const int bn = blockIdx.y * BN;
    const int tc = (tid % (BN / TN)) * TN;
    const int tr = (tid / (BN / TN)) * TM;

    float acc[TM][TN];
    #pragma unroll
    for (int m = 0; m < TM; m++)
        #pragma unroll
        for (int n = 0; n < TN; n++) acc[m][n] = 0.f;

    for (int k0 = 0; k0 < K; k0 += BK) {
        for (int i = tid; i < BM * BK; i += THREADS) {
            int r = i / BK, c = i % BK;
            int gr = bm + r;
            int j  = k0 + c;
            int ky = j / (3 * BC_);
            int kx = (j / BC_) % 3;
            int ci = j & (BC_ - 1);
            int b  = gr / S_;
            int rem = gr - b * S_;
            int h  = rem / W_;
            int w  = rem - h * W_;
            int ih = h + ky - 1, iw = w + kx - 1;
            float val = 0.f;
            if (gr < M && (unsigned)ih < (unsigned)H_ && (unsigned)iw < (unsigned)W_)
                val = In[(((size_t)b * H_ + ih) * W_ + iw) * BC_ + ci];
            As[c][r] = val;
        }
        for (int i = tid; i < BK * BN; i += THREADS) {
            int r = i / BN, c = i % BN;
            Bs[r][c] = Wt[(size_t)(k0 + r) * BC_ + bn + c];
        }
        __syncthreads();
        #pragma unroll
        for (int kk = 0; kk < BK; kk++) {
            float av[TM], bv[TN];
            #pragma unroll
            for (int m = 0; m < TM; m++) av[m] = As[kk][tr + m];
            #pragma unroll
            for (int n = 0; n < TN; n++) bv[n] = Bs[kk][tc + n];
            #pragma unroll
            for (int m = 0; m < TM; m++)
                #pragma unroll
                for (int n = 0; n < TN; n++)
                    acc[m][n] = fmaf(av[m], bv[n], acc[m][n]);
        }
        __syncthreads();
    }

    #pragma unroll
    for (int m = 0; m < TM; m++) {
        int gr = bm + tr + m;
        if (gr >= M) continue;
        #pragma unroll
        for (int n = 0; n < TN; n++) {
            int gc = bn + tc + n;
            Out[(size_t)gr * BC_ + gc] = acc[m][n];
        }
    }
}

// ---------------- layernorm (+ optional gelu / residual) -------------------
// mode 0: out = LN(x)*w+b
// mode 1: out = gelu(LN(x)*w+b)
// mode 2: out = res + LN(x)*w+b
__global__ void ln_kernel(const float* __restrict__ x, const float* __restrict__ w,
                          const float* __restrict__ bp, float* __restrict__ out,
                          int Cw, float eps, int mode, const float* __restrict__ res)
{
    __shared__ float red1[32], red2[32];
    __shared__ float stats[2];
    const int row  = blockIdx.x;
    const int tid  = threadIdx.x;
    const int lane = tid & 31, wid = tid >> 5;
    const float* xr = x + (size_t)row * Cw;

    float s = 0.f, sq = 0.f;
    for (int i = tid; i < Cw; i += blockDim.x) { float t = xr[i]; s += t; sq += t * t; }
    #pragma unroll
    for (int o = 16; o; o >>= 1) {
        s  += __shfl_down_sync(0xffffffffu, s, o);
        sq += __shfl_down_sync(0xffffffffu, sq, o);
    }
    if (lane == 0) { red1[wid] = s; red2[wid] = sq; }
    __syncthreads();
    if (tid == 0) {
        float S = 0.f, Q = 0.f;
        int nw = blockDim.x >> 5;
        for (int i = 0; i < nw; i++) { S += red1[i]; Q += red2[i]; }
        float mean = S / Cw;
        float var  = Q / Cw - mean * mean;
        stats[0] = mean;
        stats[1] = rsqrtf(var + eps);
    }
    __syncthreads();
    const float mean = stats[0], rstd = stats[1];
    for (int i = tid; i < Cw; i += blockDim.x) {
        float y = (xr[i] - mean) * rstd * w[i] + bp[i];
        if (mode == 1) y = gelu_f(y);
        else if (mode == 2) y += res[(size_t)row * Cw + i];
        out[(size_t)row * Cw + i] = y;
    }
}

// ---------------- softmax over last axis (784) ------------------------------
__global__ void softmax_k(float* __restrict__ a, int Ncol)
{
    __shared__ float red[32];
    __shared__ float sval;
    const size_t row = blockIdx.x;
    float* p = a + row * (size_t)Ncol;
    const int tid = threadIdx.x, lane = tid & 31, wid = tid >> 5;

    float m = -1e30f;
    for (int i = tid; i < Ncol; i += blockDim.x) m = fmaxf(m, p[i]);
    #pragma unroll
    for (int o = 16; o; o >>= 1) m = fmaxf(m, __shfl_xor_sync(0xffffffffu, m, o));
    if (lane == 0) red[wid] = m;
    __syncthreads();
    if (tid == 0) {
        float mm = -1e30f;
        int nw = blockDim.x >> 5;
        for (int i = 0; i < nw; i++) mm = fmaxf(mm, red[i]);
        sval = mm;
    }
    __syncthreads();
    m = sval;
    __syncthreads();

    float s = 0.f;
    for (int i = tid; i < Ncol; i += blockDim.x) {
        float e = __expf(p[i] - m);
        p[i] = e;
        s += e;
    }
    #pragma unroll
    for (int o = 16; o; o >>= 1) s += __shfl_xor_sync(0xffffffffu, s, o);
    if (lane == 0) red[wid] = s;
    __syncthreads();
    if (tid == 0) {
        float ss = 0.f;
        int nw = blockDim.x >> 5;
        for (int i = 0; i < nw; i++) ss += red[i];
        sval = ss;
    }
    __syncthreads();
    const float inv = 1.f / sval;
    for (int i = tid; i < Ncol; i += blockDim.x) p[i] *= inv;
}

// ---------------- qkv repack: [B,S,3,NH,HD] -> q[G,S,HD], kT[G,HD,S], v[G,S,HD]
__global__ void repack_k(const float* __restrict__ qkv, float* __restrict__ q,
                         float* __restrict__ kT, float* __restrict__ v)
{
    int idx = blockIdx.x * blockDim.x + threadIdx.x;
    const int total = G_ * S_ * HD_;
    if (idx >= total) return;
    int d = idx & 63;
    int s = (idx >> 6) % S_;
    int g = idx / (64 * S_);
    int b = g >> 4, n = g & 15;
    size_t src = ((size_t)(b * S_ + s)) * (3 * C_) + n * 64 + d;
    q[idx] = qkv[src];
    v[idx] = qkv[src + 2 * C_];
    kT[((size_t)g * 64 + d) * S_ + s] = qkv[src + C_];
}

// ---------------- decomposed relative position bias -------------------------
// bh[g,s,k] = sum_d q[g,s,d] * rel_h[(h - k + 27)*64 + d],  h = s / 28
// bw[g,s,l] = sum_d q[g,s,d] * rel_w[(w - l + 27)*64 + d],  w = s % 28
__global__ void relbias_k(const float* __restrict__ q,
                          const float* __restrict__ rel_h,
                          const float* __restrict__ rel_w,
                          float* __restrict__ bh, float* __restrict__ bw)
{
    const int s = blockIdx.x % S_;
    const int g = blockIdx.x / S_;
    __shared__ float qs[64];
    const int t = threadIdx.x;     // 64 threads
    qs[t] = q[((size_t)g * S_ + s) * 64 + t];
    __syncthreads();
    const int h = s / W_, w = s % W_;
    if (t < 28) {
        const float* r = rel_h + (size_t)(h - t + 27) * 64;
        float acc = 0.f;
        #pragma unroll
        for (int d = 0; d < 64; d++) acc = fmaf(qs[d], r[d], acc);
        bh[((size_t)g * S_ + s) * 28 + t] = acc;
    } else if (t >= 32 && t < 60) {
        const int l = t - 32;
        const float* r = rel_w + (size_t)(w - l + 27) * 64;
        float acc = 0.f;
        #pragma unroll
        for (int d = 0; d < 64; d++) acc = fmaf(qs[d], r[d], acc);
        bw[((size_t)g * S_ + s) * 28 + l] = acc;
    }
}

// ---------------- launch ----------------------------------------------------
extern "C" void kernel_launch(void* const* d_in, const int* in_sizes, int n_in,
                              void* d_out, int out_size)
{
    const float* x       = (const float*)d_in[0];
    const float* norm1_w = (const float*)d_in[1];
    const float* norm1_b = (const float*)d_in[2];
    const float* qkv_w   = (const float*)d_in[3];
    const float* qkv_b   = (const float*)d_in[4];
    const float* proj_w  = (const float*)d_in[5];
    const float* proj_b  = (const float*)d_in[6];
    const float* rel_h   = (const float*)d_in[7];
    const float* rel_w   = (const float*)d_in[8];
    const float* norm2_w = (const float*)d_in[9];
    const float* norm2_b = (const float*)d_in[10];
    const float* fc1_w   = (const float*)d_in[11];
    const float* fc1_b   = (const float*)d_in[12];
    const float* fc2_w   = (const float*)d_in[13];
    const float* fc2_b   = (const float*)d_in[14];
    const float* conv1_w = (const float*)d_in[15];
    const float* ln1_w   = (const float*)d_in[16];
    const float* ln1_b   = (const float*)d_in[17];
    const float* conv2_w = (const float*)d_in[18];
    const float* ln2_w   = (const float*)d_in[19];
    const float* ln2_b   = (const float*)d_in[20];
    const float* conv3_w = (const float*)d_in[21];
    const float* ln3_w   = (const float*)d_in[22];
    const float* ln3_b   = (const float*)d_in[23];
    float* out = (float*)d_out;

    float *xn, *qkv, *q, *kT, *v, *bh, *bw, *attn, *ao, *x1, *mlp, *x2;
    float *c1, *c1a, *c2, *c2a, *c3;
    cudaGetSymbolAddress((void**)&xn,   g_xn);
    cudaGetSymbolAddress((void**)&qkv,  g_qkv);
    cudaGetSymbolAddress((void**)&q,    g_q);
    cudaGetSymbolAddress((void**)&kT,   g_kT);
    cudaGetSymbolAddress((void**)&v,    g_v);
    cudaGetSymbolAddress((void**)&bh,   g_bh);
    cudaGetSymbolAddress((void**)&bw,   g_bw);
    cudaGetSymbolAddress((void**)&attn, g_attn);
    cudaGetSymbolAddress((void**)&ao,   g_ao);
    cudaGetSymbolAddress((void**)&x1,   g_x1);
    cudaGetSymbolAddress((void**)&mlp,  g_mlp);
    cudaGetSymbolAddress((void**)&x2,   g_x2);
    cudaGetSymbolAddress((void**)&c1,   g_c1);
    cudaGetSymbolAddress((void**)&c1a,  g_c1a);
    cudaGetSymbolAddress((void**)&c2,   g_c2);
    cudaGetSymbolAddress((void**)&c2a,  g_c2a);
    cudaGetSymbolAddress((void**)&c3,   g_c3);

    // 1. LN1:  x -> xn
    ln_kernel<<<M_, 256>>>(x, norm1_w, norm1_b, xn, C_, 1e-5f, 0, nullptr);

    // 2. qkv GEMM: [6272,1024] @ [1024,3072] + bias -> qkv
    sgemm_k<128,128,8,8,8,0><<<dim3(M_/128, 3*C_/128, 1), 256>>>(
        xn, qkv_w, qkv, M_, 3*C_, C_, C_, 3*C_, 3*C_,
        0, 0, 0, qkv_b, nullptr, 0, 1.f, nullptr, nullptr);

    // 3. repack q / kT / v
    repack_k<<<(G_*S_*HD_ + 255)/256, 256>>>(qkv, q, kT, v);

    // 4. relative-position bias dots
    relbias_k<<<G_*S_, 64>>>(q, rel_h, rel_w, bh, bw);

    // 5. scores: attn = SCALE * q @ kT + bias_h + bias_w   (batched over 128)
    sgemm_k<128,128,8,8,8,3><<<dim3((S_+127)/128, (S_+127)/128, G_), 256>>>(
        q, kT, attn, S_, S_, HD_, HD_, S_, S_,
        (long long)S_*HD_, (long long)HD_*S_, (long long)S_*S_,
        nullptr, nullptr, 0, SCALE_, bh, bw);

    // 6. softmax rows
    softmax_k<<<G_*S_, 256>>>(attn, S_);

    // 7. AV: out[g] = attn[g] @ v[g], scattered into [B,S,C]
    sgemm_k<128,64,8,8,4,4><<<dim3((S_+127)/128, 1, G_), 256>>>(
        attn, v, ao, S_, HD_, S_, S_, HD_, 0,
        (long long)S_*S_, (long long)S_*HD_, 0,
        nullptr, nullptr, 0, 1.f, nullptr, nullptr);

    // 8. proj + residual: x1 = x + ao @ proj_w + proj_b
    sgemm_k<128,128,8,8,8,2><<<dim3(M_/128, C_/128, 1), 256>>>(
        ao, proj_w, x1, M_, C_, C_, C_, C_, C_,
        0, 0, 0, proj_b, x, C_, 1.f, nullptr, nullptr);

    // 9. LN2: x1 -> xn
    ln_kernel<<<M_, 256>>>(x1, norm2_w, norm2_b, xn, C_, 1e-5f, 0, nullptr);

    // 10. fc1 + gelu
    sgemm_k<128,128,8,8,8,1><<<dim3(M_/128, HID_/128, 1), 256>>>(
        xn, fc1_w, mlp, M_, HID_, C_, C_, HID_, HID_,
        0, 0, 0, fc1_b, nullptr, 0, 1.f, nullptr, nullptr);

    // 11. fc2 + residual: x2 = x1 + mlp @ fc2_w + fc2_b
    sgemm_k<128,128,8,8,8,2><<<dim3(M_/128, C_/128, 1), 256>>>(
        mlp, fc2_w, x2, M_, C_, HID_, HID_, C_, C_,
        0, 0, 0, fc2_b, x1, C_, 1.f, nullptr, nullptr);

    // 12. conv1 (1x1): c1 = x2 @ conv1_w
    sgemm_k<128,128,8,8,8,0><<<dim3(M_/128, BC_/128, 1), 256>>>(
        x2, conv1_w, c1, M_, BC_, C_, C_, BC_, BC_,
        0, 0, 0, nullptr, nullptr, 0, 1.f, nullptr, nullptr);

    // 13. LN(512, eps 1e-6) + gelu
    ln_kernel<<<M_, 256>>>(c1, ln1_w, ln1_b, c1a, BC_, 1e-6f, 1, nullptr);

    // 14. conv2 (3x3 implicit GEMM)
    conv3x3_k<128,128,8,8,8><<<dim3(M_/128, BC_/128, 1), 256>>>(c1a, conv2_w, c2);

    // 15. LN + gelu
    ln_kernel<<<M_, 256>>>(c2, ln2_w, ln2_b, c2a, BC_, 1e-6f, 1, nullptr);

    // 16. conv3 (1x1): c3 = c2a @ conv3_w
    sgemm_k<128,128,8,8,8,0><<<dim3(M_/128, C_/128, 1), 256>>>(
        c2a, conv3_w, c3, M_, C_, BC_, BC_, C_, C_,
        0, 0, 0, nullptr, nullptr, 0, 1.f, nullptr, nullptr);

    // 17. final: out = x2 + LN(c3)*ln3_w + ln3_b
    ln_kernel<<<M_, 256>>>(c3, ln3_w, ln3_b, out, C_, 1e-6f, 2, x2);
}

// round 4
// speedup vs baseline: 2.7006x; 2.7006x over previous
#include <cuda_runtime.h>
#include <cuda_bf16.h>
#include <mma.h>
#include <math.h>
#include <stdint.h>

using namespace nvcuda;
typedef __nv_bfloat16 bf16;
constexpr int C_=1024, S_=784, M_=6272, HID_=4096, BC_=512, G_=128;

__device__ __align__(16) bf16 g_xnh[M_*C_], g_xnl[M_*C_];
__device__ __align__(16) float g_qkv[M_*3*C_];
__device__ __align__(16) bf16 g_qh[G_*S_*64], g_ql[G_*S_*64], g_kh[G_*S_*64], g_kl[G_*S_*64];
__device__ __align__(16) bf16 g_vTh[G_*64*S_], g_vTl[G_*64*S_];
__device__ __align__(16) float g_bh[G_*S_*28], g_bw[G_*S_*28];
__device__ __align__(16) float g_attn[(size_t)G_*S_*S_];
__device__ __align__(16) bf16 g_ah[(size_t)G_*S_*S_], g_al[(size_t)G_*S_*S_];
__device__ __align__(16) bf16 g_aoh[M_*C_], g_aol[M_*C_];
__device__ __align__(16) float g_x1[M_*C_];
__device__ __align__(16) bf16 g_mh[M_*HID_], g_ml[M_*HID_];
__device__ __align__(16) float g_x2[M_*C_];
__device__ __align__(16) bf16 g_x2h[M_*C_], g_x2l[M_*C_];
__device__ __align__(16) float g_c1[M_*BC_];
__device__ __align__(16) bf16 g_c1h[M_*BC_], g_c1l[M_*BC_];
__device__ __align__(16) float g_c2[M_*BC_];
__device__ __align__(16) bf16 g_c2h[M_*BC_], g_c2l[M_*BC_];
__device__ __align__(16) float g_c3[M_*C_];
__device__ __align__(16) bf16 g_wah[3*C_*C_], g_wal[3*C_*C_];
__device__ __align__(16) bf16 g_wbh[C_*C_],  g_wbl[C_*C_];
__device__ __align__(16) bf16 g_wch[HID_*C_],g_wcl[HID_*C_];
__device__ __align__(16) bf16 g_wdh[C_*HID_],g_wdl[C_*HID_];
__device__ __align__(16) bf16 g_weh[BC_*C_], g_wel[BC_*C_];
__device__ __align__(16) bf16 g_wfh[BC_*9*BC_], g_wfl[BC_*9*BC_];
__device__ __align__(16) bf16 g_wgh[C_*BC_], g_wgl[C_*BC_];

__device__ __forceinline__ float gelu_f(float x){ return 0.5f*x*(1.0f+erff(x*0.7071067811865475f)); }
__device__ __forceinline__ void split2(float x, bf16&h, bf16&l){ h=__float2bfloat16(x); l=__float2bfloat16(x-__bfloat162float(h)); }

// copy [rows x 32] bf16 chunk into smem (stride 40), zero-fill OOB
__device__ __forceinline__ void load_tile(const bf16* __restrict__ src, int ld,
        int row0, int rmax, int k0, int K, bf16* sm, int tid, int rows){
    for (int i = tid; i < rows*4; i += 256){
        int r = i>>2, cq = i&3;
        int gr = row0 + r, gk = k0 + (cq<<3);
        uint4 v = make_uint4(0,0,0,0);
        if (gr < rmax && gk < K) v = *reinterpret_cast<const uint4*>(src + (size_t)gr*ld + gk);
        *reinterpret_cast<uint4*>(sm + r*40 + (cq<<3)) = v;
    }
}
__device__ __forceinline__ void load_conv(const bf16* __restrict__ src, int row0, int k0,
        bf16* sm, int tid){
    int ky = k0/1536, kxr = k0 - ky*1536, kx = kxr>>9, ci0 = kxr&511;
    for (int i = tid; i < 512; i += 256){
        int r = i>>2, cq = i&3;
        int gr = row0 + r;
        uint4 v = make_uint4(0,0,0,0);
        if (gr < M_){
            int b = gr/S_, rem = gr - b*S_, h = rem/28, w = rem - h*28;
            int ih = h+ky-1, iw = w+kx-1;
            if ((unsigned)ih<28u && (unsigned)iw<28u)
                v = *reinterpret_cast<const uint4*>(src + ((size_t)((b*28+ih)*28+iw))*BC_ + ci0 + (cq<<3));
        }
        *reinterpret_cast<uint4*>(sm + r*40 + (cq<<3)) = v;
    }
}

// bf16x3 wmma GEMM: D = (Ah+Al)@(Bh+Bl)^T (drop AlBl). B given as [N,K].
// EPI 0: fp32(+bias)  1: gelu->split  2: +bias+res->fp32  3: +bh+bw->fp32
// EPI 4: split scatter to [B,S,C]     5: +bias+res->fp32 AND split
template<int BN, int EPI, int GATHER>
__global__ void __launch_bounds__(256,2) mma_gemm(
    const bf16* __restrict__ Ah, const bf16* __restrict__ Al,
    const bf16* __restrict__ Bh, const bf16* __restrict__ Bl,
    float* __restrict__ o0, bf16* __restrict__ o1, bf16* __restrict__ o2,
    int M, int N, int K, int lda, int ldb, int ldc,
    long long sA, long long sB, long long sC,
    const float* __restrict__ bias, const float* __restrict__ res, int ldres,
    const float* __restrict__ bhp, const float* __restrict__ bwp)
{
    constexpr int BM = 128;
    constexpr int WarpsN = (BN==128)?4:2;
    constexpr int WarpsM = 8/WarpsN;
    constexpr int WM = BM/WarpsM, WN = BN/WarpsN;
    constexpr int MI = WM/16, NI = WN/16;
    constexpr int ATILE = BM*40, BTILE = BN*40;   // elements
    __shared__ __align__(128) bf16 pool[2*ATILE + 2*BTILE];
    bf16 *Ash = pool, *Asl = pool+ATILE, *Bsh = pool+2*ATILE, *Bsl = pool+2*ATILE+BTILE;

    const int tid = threadIdx.x, warp = tid>>5, lane = tid&31;
    const int bm = blockIdx.x*BM, bn = blockIdx.y*BN, g = blockIdx.z;
    Ah += (size_t)g*sA; Al += (size_t)g*sA; Bh += (size_t)g*sB; Bl += (size_t)g*sB;
    const int wrow = (warp/WarpsN)*WM, wcol = (warp%WarpsN)*WN;

    wmma::fragment<wmma::accumulator,16,16,16,float> acc[MI][NI];
    #pragma unroll
    for (int mi=0; mi<MI; mi++)
        #pragma unroll
        for (int ni=0; ni<NI; ni++) wmma::fill_fragment(acc[mi][ni], 0.f);

    const int KC = (K+31)>>5;
    for (int kc = 0; kc < KC; kc++){
        int k0 = kc<<5;
        if (GATHER){ load_conv(Ah, bm, k0, Ash, tid); load_conv(Al, bm, k0, Asl, tid); }
        else { load_tile(Ah, lda, bm, M, k0, K, Ash, tid, BM);
               load_tile(Al, lda, bm, M, k0, K, Asl, tid, BM); }
        load_tile(Bh, ldb, bn, N, k0, K, Bsh, tid, BN);
        load_tile(Bl, ldb, bn, N, k0, K, Bsl, tid, BN);
        __syncthreads();
        #pragma unroll
        for (int ks=0; ks<2; ks++){
            wmma::fragment<wmma::matrix_b,16,16,16,bf16,wmma::col_major> bh_f[NI], bl_f[NI];
            #pragma unroll
            for (int ni=0; ni<NI; ni++){
                wmma::load_matrix_sync(bh_f[ni], Bsh + (wcol+ni*16)*40 + ks*16, 40);
                wmma::load_matrix_sync(bl_f[ni], Bsl + (wcol+ni*16)*40 + ks*16, 40);
            }
            #pragma unroll
            for (int mi=0; mi<MI; mi++){
                wmma::fragment<wmma::matrix_a,16,16,16,bf16,wmma::row_major> ah_f, al_f;
                wmma::load_matrix_sync(ah_f, Ash + (wrow+mi*16)*40 + ks*16, 40);
                wmma::load_matrix_sync(al_f, Asl + (wrow+mi*16)*40 + ks*16, 40);
                #pragma unroll
                for (int ni=0; ni<NI; ni++){
                    wmma::mma_sync(acc[mi][ni], ah_f, bh_f[ni], acc[mi][ni]);
                    wmma::mma_sync(acc[mi][ni], al_f, bh_f[ni], acc[mi][ni]);
                    wmma::mma_sync(acc[mi][ni], ah_f, bl_f[ni], acc[mi][ni]);
                }
            }
        }
        __syncthreads();
    }

    // epilogue: fragment -> per-warp smem staging -> global with fused op
    float* eb = reinterpret_cast<float*>(pool) + warp*320;   // 16x20
    #pragma unroll
    for (int mi=0; mi<MI; mi++){
        #pragma unroll
        for (int ni=0; ni<NI; ni++){
            wmma::store_matrix_sync(eb, acc[mi][ni], 20, wmma::mem_row_major);
            __syncwarp();
            int row0 = bm + wrow + mi*16, col0 = bn + wcol + ni*16;
            #pragma unroll
            for (int j=0; j<8; j++){
                int e = lane + j*32, r = e>>4, c = e&15;
                int gr = row0 + r, gc = col0 + c;
                if (gr < M && gc < N){
                    float v = eb[r*20 + c];
                    if (bias) v += bias[gc];
                    if (EPI == 1){ v = gelu_f(v); bf16 h,l; split2(v,h,l);
                        o1[(size_t)gr*ldc+gc]=h; o2[(size_t)gr*ldc+gc]=l; }
                    else if (EPI == 2){ o0[(size_t)gr*ldc+gc] = v + res[(size_t)gr*ldres+gc]; }
                    else if (EPI == 3){
                        v += bhp[((size_t)g*S_+gr)*28 + gc/28] + bwp[((size_t)g*S_+gr)*28 + gc%28];
                        o0[(size_t)g*sC + (size_t)gr*ldc + gc] = v; }
                    else if (EPI == 4){
                        size_t o = ((size_t)(g>>4)*S_ + gr)*1024 + (size_t)(g&15)*64 + gc;
                        bf16 h,l; split2(v,h,l); o1[o]=h; o2[o]=l; }
                    else if (EPI == 5){ v += res[(size_t)gr*ldres+gc];
                        o0[(size_t)gr*ldc+gc] = v; bf16 h,l; split2(v,h,l);
                        o1[(size_t)gr*ldc+gc]=h; o2[(size_t)gr*ldc+gc]=l; }
                    else o0[(size_t)g*sC + (size_t)gr*ldc + gc] = v;
                }
            }
            __syncwarp();
        }
    }
}

__global__ void ln_k(const float* __restrict__ x, const float* __restrict__ w,
                     const float* __restrict__ bp, float* __restrict__ of,
                     bf16* __restrict__ oh, bf16* __restrict__ ol,
                     int Cw, float eps, int mode, const float* __restrict__ res)
{
    __shared__ float r1[8], r2[8], st[2];
    const int row = blockIdx.x, tid = threadIdx.x, lane = tid&31, wd = tid>>5;
    const float* xr = x + (size_t)row*Cw;
    float s=0.f, sq=0.f;
    for (int i = tid; i < Cw; i += 256){ float t = xr[i]; s += t; sq += t*t; }
    #pragma unroll
    for (int o=16;o;o>>=1){ s+=__shfl_down_sync(~0u,s,o); sq+=__shfl_down_sync(~0u,sq,o); }
    if (lane==0){ r1[wd]=s; r2[wd]=sq; }
    __syncthreads();
    if (tid==0){ float S=0,Q=0; for(int i=0;i<8;i++){S+=r1[i];Q+=r2[i];}
        float m=S/Cw, v=Q/Cw-m*m; st[0]=m; st[1]=rsqrtf(v+eps); }
    __syncthreads();
    float mean=st[0], rstd=st[1];
    for (int i = tid; i < Cw; i += 256){
        float y = (xr[i]-mean)*rstd*w[i] + bp[i];
        if (mode==2) of[(size_t)row*Cw+i] = y + res[(size_t)row*Cw+i];
        else { if (mode==1) y = gelu_f(y);
            bf16 h,l; split2(y,h,l); oh[(size_t)row*Cw+i]=h; ol[(size_t)row*Cw+i]=l; }
    }
}

__global__ void softmax_split_k(const float* __restrict__ a, bf16* __restrict__ ah, bf16* __restrict__ al)
{
    __shared__ float red[8]; __shared__ float bv;
    const size_t row = blockIdx.x;
    const float* p = a + row*S_;
    const int t = threadIdx.x, lane = t&31, wd = t>>5;
    float v[4]; float m = -1e30f;
    #pragma unroll
    for (int j=0;j<4;j++){ int i=t+j*256; v[j]=(i<S_)?p[i]:-1e30f; m=fmaxf(m,v[j]); }
    #pragma unroll
    for (int o=16;o;o>>=1) m=fmaxf(m,__shfl_xor_sync(~0u,m,o));
    if (lane==0) red[wd]=m;
    __syncthreads();
    if (t==0){ float mm=-1e30f; for(int i=0;i<8;i++) mm=fmaxf(mm,red[i]); bv=mm; }
    __syncthreads(); m=bv; __syncthreads();
    float s=0.f;
    #pragma unroll
    for (int j=0;j<4;j++){ int i=t+j*256; if(i<S_){ v[j]=__expf(v[j]-m); s+=v[j]; } }
    #pragma unroll
    for (int o=16;o;o>>=1) s+=__shfl_xor_sync(~0u,s,o);
    if (lane==0) red[wd]=s;
    __syncthreads();
    if (t==0){ float ss=0; for(int i=0;i<8;i++) ss+=red[i]; bv=1.f/ss; }
    __syncthreads();
    float inv=bv;
    #pragma unroll
    for (int j=0;j<4;j++){ int i=t+j*256; if(i<S_){ bf16 h,l; split2(v[j]*inv,h,l);
        ah[row*S_+i]=h; al[row*S_+i]=l; } }
}

__global__ void repack_k(const float* __restrict__ qkv,
    bf16* __restrict__ qh, bf16* __restrict__ ql, bf16* __restrict__ kh, bf16* __restrict__ kl,
    bf16* __restrict__ vTh, bf16* __restrict__ vTl)
{
    __shared__ float sv[32][65];
    const int g = blockIdx.y, s0 = blockIdx.x*32, b = g>>4, n = g&15, t = threadIdx.x;
    for (int e = t; e < 2048; e += 256){
        int sl = e>>6, d = e&63, s = s0+sl;
        if (s < S_){
            size_t base = ((size_t)(b*S_+s))*3072 + n*64 + d;
            float qv = qkv[base]*0.125f, kv = qkv[base+1024];
            sv[sl][d] = qkv[base+2048];
            size_t o = ((size_t)g*S_+s)*64 + d;
            bf16 h,l; split2(qv,h,l); qh[o]=h; ql[o]=l;
            split2(kv,h,l); kh[o]=h; kl[o]=l;
        }
    }
    __syncthreads();
    for (int e = t; e < 2048; e += 256){
        int d = e>>5, j = e&31, s = s0+j;
        if (s < S_){ bf16 h,l; split2(sv[j][d],h,l);
            size_t o = ((size_t)g*64+d)*S_ + s; vTh[o]=h; vTl[o]=l; }
    }
}

__global__ void relbias_k(const float* __restrict__ qkv, const float* __restrict__ rh,
                          const float* __restrict__ rw, float* __restrict__ bh, float* __restrict__ bw)
{
    const int s = blockIdx.x % S_, g = blockIdx.x / S_, b = g>>4, n = g&15;
    __shared__ float qs[64];
    const int t = threadIdx.x;
    qs[t] = qkv[((size_t)(b*S_+s))*3072 + n*64 + t];
    __syncthreads();
    const int h = s/28, w = s%28;
    if (t < 28){
        const float* r = rh + (size_t)(h-t+27)*64; float a=0.f;
        #pragma unroll
        for (int d=0;d<64;d++) a = fmaf(qs[d], r[d], a);
        bh[((size_t)g*S_+s)*28 + t] = a;
    } else if (t >= 32 && t < 60){
        const int l = t-32;
        const float* r = rw + (size_t)(w-l+27)*64; float a=0.f;
        #pragma unroll
        for (int d=0;d<64;d++) a = fmaf(qs[d], r[d], a);
        bw[((size_t)g*S_+s)*28 + l] = a;
    }
}

__global__ void wsplitT_k(const float* __restrict__ Wm, bf16* __restrict__ Th,
                          bf16* __restrict__ Tl, int K, int N)
{
    __shared__ float s[32][33];
    const int k0 = blockIdx.x*32, n0 = blockIdx.y*32, tx = threadIdx.x, ty = threadIdx.y;
    #pragma unroll
    for (int y=0;y<32;y+=8) s[ty+y][tx] = Wm[(size_t)(k0+ty+y)*N + n0+tx];
    __syncthreads();
    #pragma unroll
    for (int y=0;y<32;y+=8){
        bf16 h,l; split2(s[tx][ty+y],h,l);
        size_t o = (size_t)(n0+ty+y)*K + k0+tx; Th[o]=h; Tl[o]=l;
    }
}

#define GSA(p, sym) cudaGetSymbolAddress((void**)&p, sym)
extern "C" void kernel_launch(void* const* d_in, const int* in_sizes, int n_in,
                              void* d_out, int out_size)
{
    const float *x=(const float*)d_in[0], *n1w=(const float*)d_in[1], *n1b=(const float*)d_in[2],
        *qkvw=(const float*)d_in[3], *qkvb=(const float*)d_in[4], *pw=(const float*)d_in[5],
        *pb=(const float*)d_in[6], *relh=(const float*)d_in[7], *relw=(const float*)d_in[8],
        *n2w=(const float*)d_in[9], *n2b=(const float*)d_in[10], *f1w=(const float*)d_in[11],
        *f1b=(const float*)d_in[12], *f2w=(const float*)d_in[13], *f2b=(const float*)d_in[14],
        *c1w=(const float*)d_in[15], *l1w=(const float*)d_in[16], *l1b=(const float*)d_in[17],
        *c2w=(const float*)d_in[18], *l2w=(const float*)d_in[19], *l2b=(const float*)d_in[20],
        *c3w=(const float*)d_in[21], *l3w=(const float*)d_in[22], *l3b=(const float*)d_in[23];
    float* out = (float*)d_out;

    float *qkv,*bh,*bw,*attn,*x1,*x2,*c1,*c2,*c3;
    bf16 *xnh,*xnl,*qh,*ql,*kh,*kl,*vTh,*vTl,*ah,*al,*aoh,*aol,*mh,*ml,*x2h,*x2l,*c1h,*c1l,*c2h,*c2l;
    bf16 *wah,*wal,*wbh,*wbl,*wch,*wcl,*wdh,*wdl,*weh,*wel,*wfh,*wfl,*wgh,*wgl;
    GSA(qkv,g_qkv); GSA(bh,g_bh); GSA(bw,g_bw); GSA(attn,g_attn); GSA(x1,g_x1); GSA(x2,g_x2);
    GSA(c1,g_c1); GSA(c2,g_c2); GSA(c3,g_c3);
    GSA(xnh,g_xnh); GSA(xnl,g_xnl); GSA(qh,g_qh); GSA(ql,g_ql); GSA(kh,g_kh); GSA(kl,g_kl);
    GSA(vTh,g_vTh); GSA(vTl,g_vTl); GSA(ah,g_ah); GSA(al,g_al); GSA(aoh,g_aoh); GSA(aol,g_aol);
    GSA(mh,g_mh); GSA(ml,g_ml); GSA(x2h,g_x2h); GSA(x2l,g_x2l);
    GSA(c1h,g_c1h); GSA(c1l,g_c1l); GSA(c2h,g_c2h); GSA(c2l,g_c2l);
    GSA(wah,g_wah); GSA(wal,g_wal); GSA(wbh,g_wbh); GSA(wbl,g_wbl); GSA(wch,g_wch); GSA(wcl,g_wcl);
    GSA(wdh,g_wdh); GSA(wdl,g_wdl); GSA(weh,g_weh); GSA(wel,g_wel); GSA(wfh,g_wfh); GSA(wfl,g_wfl);
    GSA(wgh,g_wgh); GSA(wgl,g_wgl);

    dim3 wb(32,8);
    wsplitT_k<<<dim3(32,96), wb>>>(qkvw, wah, wal, C_, 3*C_);
    wsplitT_k<<<dim3(32,32), wb>>>(pw,  wbh, wbl, C_, C_);
    wsplitT_k<<<dim3(32,128),wb>>>(f1w, wch, wcl, C_, HID_);
    wsplitT_k<<<dim3(128,32),wb>>>(f2w, wdh, wdl, HID_, C_);
    wsplitT_k<<<dim3(32,16), wb>>>(c1w, weh, wel, C_, BC_);
    wsplitT_k<<<dim3(144,16),wb>>>(c2w, wfh, wfl, 9*BC_, BC_);
    wsplitT_k<<<dim3(16,32), wb>>>(c3w, wgh, wgl, BC_, C_);

    ln_k<<<M_,256>>>(x, n1w, n1b, nullptr, xnh, xnl, C_, 1e-5f, 0, nullptr);
    mma_gemm<128,0,0><<<dim3(49,24,1),256>>>(xnh,xnl,wah,wal, qkv,nullptr,nullptr,
        M_,3*C_,C_, C_,C_,3*C_, 0,0,0, qkvb,nullptr,0,nullptr,nullptr);
    repack_k<<<dim3(25,G_),256>>>(qkv,qh,ql,kh,kl,vTh,vTl);
    relbias_k<<<G_*S_,64>>>(qkv,relh,relw,bh,bw);
    mma_gemm<128,3,0><<<dim3(7,7,G_),256>>>(qh,ql,kh,kl, attn,nullptr,nullptr,
        S_,S_,64, 64,64,S_, (long long)S_*64,(long long)S_*64,(long long)S_*S_,
        nullptr,nullptr,0,bh,bw);
    softmax_split_k<<<G_*S_,256>>>(attn,ah,al);
    mma_gemm<64,4,0><<<dim3(7,1,G_),256>>>(ah,al,vTh,vTl, nullptr,aoh,aol,
        S_,64,S_, S_,S_,0, (long long)S_*S_,(long long)64*S_,0,
        nullptr,nullptr,0,nullptr,nullptr);
    mma_gemm<128,2,0><<<dim3(49,8,1),256>>>(aoh,aol,wbh,wbl, x1,nullptr,nullptr,
        M_,C_,C_, C_,C_,C_, 0,0,0, pb,x,C_,nullptr,nullptr);
    ln_k<<<M_,256>>>(x1, n2w, n2b, nullptr, xnh, xnl, C_, 1e-5f, 0, nullptr);
    mma_gemm<128,1,0><<<dim3(49,32,1),256>>>(xnh,xnl,wch,wcl, nullptr,mh,ml,
        M_,HID_,C_, C_,C_,HID_, 0,0,0, f1b,nullptr,0,nullptr,nullptr);
    mma_gemm<128,5,0><<<dim3(49,8,1),256>>>(mh,ml,wdh,wdl, x2,x2h,x2l,
        M_,C_,HID_, HID_,HID_,C_, 0,0,0, f2b,x1,C_,nullptr,nullptr);
    mma_gemm<128,0,0><<<dim3(49,4,1),256>>>(x2h,x2l,weh,wel, c1,nullptr,nullptr,
        M_,BC_,C_, C_,C_,BC_, 0,0,0, nullptr,nullptr,0,nullptr,nullptr);
    ln_k<<<M_,256>>>(c1, l1w, l1b, nullptr, c1h, c1l, BC_, 1e-6f, 1, nullptr);
    mma_gemm<128,0,1><<<dim3(49,4,1),256>>>(c1h,c1l,wfh,wfl, c2,nullptr,nullptr,
        M_,BC_,9*BC_, 0,9*BC_,BC_, 0,0,0, nullptr,nullptr,0,nullptr,nullptr);
    ln_k<<<M_,256>>>(c2, l2w, l2b, nullptr, c2h, c2l, BC_, 1e-6f, 1, nullptr);
    mma_gemm<128,0,0><<<dim3(49,8,1),256>>>(c2h,c2l,wgh,wgl, c3,nullptr,nullptr,
        M_,C_,BC_, BC_,BC_,C_, 0,0,0, nullptr,nullptr,0,nullptr,nullptr);
    ln_k<<<M_,256>>>(c3, l3w, l3b, out, nullptr, nullptr, C_, 1e-6f, 2, x2);
}

// round 5
// speedup vs baseline: 3.4139x; 1.2641x over previous
#include <cuda_runtime.h>
#include <cuda_bf16.h>
#include <mma.h>
#include <math.h>
#include <stdint.h>

using namespace nvcuda;
typedef __nv_bfloat16 bf16;
constexpr int C_=1024, S_=784, M_=6272, HID_=4096, BC_=512, G_=128;

__device__ __align__(16) bf16 g_xnh[M_*C_], g_xnl[M_*C_];
__device__ __align__(16) float g_qkv[M_*3*C_];
__device__ __align__(16) bf16 g_qh[G_*S_*64], g_ql[G_*S_*64], g_kh[G_*S_*64], g_kl[G_*S_*64];
__device__ __align__(16) bf16 g_vTh[G_*64*S_], g_vTl[G_*64*S_];
__device__ __align__(16) float g_bh[G_*S_*28], g_bw[G_*S_*28];
__device__ __align__(16) float g_attn[(size_t)G_*S_*S_];
__device__ __align__(16) bf16 g_ah[(size_t)G_*S_*S_], g_al[(size_t)G_*S_*S_];
__device__ __align__(16) bf16 g_aoh[M_*C_], g_aol[M_*C_];
__device__ __align__(16) float g_x1[M_*C_];
__device__ __align__(16) bf16 g_mh[M_*HID_], g_ml[M_*HID_];
__device__ __align__(16) float g_x2[M_*C_];
__device__ __align__(16) bf16 g_x2h[M_*C_], g_x2l[M_*C_];
__device__ __align__(16) float g_c1[M_*BC_];
__device__ __align__(16) bf16 g_c1h[M_*BC_], g_c1l[M_*BC_];
__device__ __align__(16) float g_c2[M_*BC_];
__device__ __align__(16) bf16 g_c2h[M_*BC_], g_c2l[M_*BC_];
__device__ __align__(16) float g_c3[M_*C_];
__device__ __align__(16) bf16 g_wah[3*C_*C_], g_wal[3*C_*C_];
__device__ __align__(16) bf16 g_wbh[C_*C_],  g_wbl[C_*C_];
__device__ __align__(16) bf16 g_wch[HID_*C_],g_wcl[HID_*C_];
__device__ __align__(16) bf16 g_wdh[C_*HID_],g_wdl[C_*HID_];
__device__ __align__(16) bf16 g_weh[BC_*C_], g_wel[BC_*C_];
__device__ __align__(16) bf16 g_wfh[BC_*9*BC_], g_wfl[BC_*9*BC_];
__device__ __align__(16) bf16 g_wgh[C_*BC_], g_wgl[C_*BC_];

__device__ __forceinline__ float gelu_f(float x){ return 0.5f*x*(1.0f+erff(x*0.7071067811865475f)); }
__device__ __forceinline__ void split2(float x, bf16&h, bf16&l){ h=__float2bfloat16(x); l=__float2bfloat16(x-__bfloat162float(h)); }

__device__ __forceinline__ void cp16(bf16* sm, const bf16* gm, bool pred){
    uint32_t sa = (uint32_t)__cvta_generic_to_shared(sm);
    int sz = pred ? 16 : 0;
    asm volatile("cp.async.ca.shared.global [%0], [%1], 16, %2;" :: "r"(sa), "l"(gm), "r"(sz));
}
#define CP_COMMIT() asm volatile("cp.async.commit_group;")

// async-stage [rows x 32] bf16 chunk into smem (stride 40)
__device__ __forceinline__ void stage_tile(const bf16* __restrict__ src, int ld,
        int row0, int rmax, int k0, int K, bf16* sm, int tid, int rows){
    for (int i = tid; i < rows*4; i += 256){
        int r = i>>2, cq = i&3;
        int gr = row0 + r, gk = k0 + (cq<<3);
        bool p = (gr < rmax && gk < K);
        cp16(sm + r*40 + (cq<<3), p ? src + (size_t)gr*ld + gk : src, p);
    }
}
__device__ __forceinline__ void stage_conv(const bf16* __restrict__ src, int row0, int k0,
        bf16* sm, int tid){
    int ky = k0/1536, kxr = k0 - ky*1536, kx = kxr>>9, ci0 = kxr&511;
    for (int i = tid; i < 512; i += 256){
        int r = i>>2, cq = i&3;
        int gr = row0 + r;
        bool p = false; const bf16* g = src;
        if (gr < M_){
            int b = gr/S_, rem = gr - b*S_, h = rem/28, w = rem - h*28;
            int ih = h+ky-1, iw = w+kx-1;
            if ((unsigned)ih<28u && (unsigned)iw<28u){
                p = true; g = src + ((size_t)((b*28+ih)*28+iw))*BC_ + ci0 + (cq<<3);
            }
        }
        cp16(sm + r*40 + (cq<<3), g, p);
    }
}

// bf16x3 wmma GEMM, 2-stage cp.async pipeline. B given as [N,K].
// EPI 0: fp32(+bias)  1: gelu->split  2: +bias+res->fp32  3: +bh+bw->fp32
// EPI 4: split scatter to [B,S,C]     5: +bias+res->fp32 AND split
template<int BN, int EPI, int GATHER>
__global__ void __launch_bounds__(256) mma_gemm(
    const bf16* __restrict__ Ah, const bf16* __restrict__ Al,
    const bf16* __restrict__ Bh, const bf16* __restrict__ Bl,
    float* __restrict__ o0, bf16* __restrict__ o1, bf16* __restrict__ o2,
    int M, int N, int K, int lda, int ldb, int ldc,
    long long sA, long long sB, long long sC,
    const float* __restrict__ bias, const float* __restrict__ res, int ldres,
    const float* __restrict__ bhp, const float* __restrict__ bwp)
{
    constexpr int BM = 128;
    constexpr int WarpsN = (BN==128)?4:2;
    constexpr int WarpsM = 8/WarpsN;
    constexpr int WM = BM/WarpsM, WN = BN/WarpsN;
    constexpr int MI = WM/16, NI = WN/16;
    constexpr int ATILE = BM*40, BTILE = BN*40;
    constexpr int STAGE = 2*ATILE + 2*BTILE;
    extern __shared__ __align__(128) bf16 pool[];

    const int tid = threadIdx.x, warp = tid>>5, lane = tid&31;
    const int bm = blockIdx.x*BM, bn = blockIdx.y*BN, g = blockIdx.z;
    Ah += (size_t)g*sA; Al += (size_t)g*sA; Bh += (size_t)g*sB; Bl += (size_t)g*sB;
    const int wrow = (warp/WarpsN)*WM, wcol = (warp%WarpsN)*WN;

    wmma::fragment<wmma::accumulator,16,16,16,float> acc[MI][NI];
    #pragma unroll
    for (int mi=0; mi<MI; mi++)
        #pragma unroll
        for (int ni=0; ni<NI; ni++) wmma::fill_fragment(acc[mi][ni], 0.f);

    const int KC = (K+31)>>5;
    auto issue = [&](int kc, int s){
        bf16* st = pool + s*STAGE;
        int k0 = kc<<5;
        if (GATHER){ stage_conv(Ah, bm, k0, st, tid); stage_conv(Al, bm, k0, st+ATILE, tid); }
        else { stage_tile(Ah, lda, bm, M, k0, K, st, tid, BM);
               stage_tile(Al, lda, bm, M, k0, K, st+ATILE, tid, BM); }
        stage_tile(Bh, ldb, bn, N, k0, K, st+2*ATILE, tid, BN);
        stage_tile(Bl, ldb, bn, N, k0, K, st+2*ATILE+BTILE, tid, BN);
        CP_COMMIT();
    };
    issue(0, 0);
    for (int kc = 0; kc < KC; kc++){
        int buf = kc & 1;
        if (kc+1 < KC){
            issue(kc+1, buf^1);
            asm volatile("cp.async.wait_group 1;");
        } else {
            asm volatile("cp.async.wait_group 0;");
        }
        __syncthreads();
        bf16 *Ash = pool + buf*STAGE, *Asl = Ash + ATILE;
        bf16 *Bsh = Ash + 2*ATILE,    *Bsl = Ash + 2*ATILE + BTILE;
        #pragma unroll
        for (int ks=0; ks<2; ks++){
            wmma::fragment<wmma::matrix_b,16,16,16,bf16,wmma::col_major> bh_f[NI], bl_f[NI];
            #pragma unroll
            for (int ni=0; ni<NI; ni++){
                wmma::load_matrix_sync(bh_f[ni], Bsh + (wcol+ni*16)*40 + ks*16, 40);
                wmma::load_matrix_sync(bl_f[ni], Bsl + (wcol+ni*16)*40 + ks*16, 40);
            }
            #pragma unroll
            for (int mi=0; mi<MI; mi++){
                wmma::fragment<wmma::matrix_a,16,16,16,bf16,wmma::row_major> ah_f, al_f;
                wmma::load_matrix_sync(ah_f, Ash + (wrow+mi*16)*40 + ks*16, 40);
                wmma::load_matrix_sync(al_f, Asl + (wrow+mi*16)*40 + ks*16, 40);
                #pragma unroll
                for (int ni=0; ni<NI; ni++){
                    wmma::mma_sync(acc[mi][ni], ah_f, bh_f[ni], acc[mi][ni]);
                    wmma::mma_sync(acc[mi][ni], al_f, bh_f[ni], acc[mi][ni]);
                    wmma::mma_sync(acc[mi][ni], ah_f, bl_f[ni], acc[mi][ni]);
                }
            }
        }
        __syncthreads();
    }

    float* eb = reinterpret_cast<float*>(pool) + warp*320;   // 16x20
    #pragma unroll
    for (int mi=0; mi<MI; mi++){
        #pragma unroll
        for (int ni=0; ni<NI; ni++){
            wmma::store_matrix_sync(eb, acc[mi][ni], 20, wmma::mem_row_major);
            __syncwarp();
            int row0 = bm + wrow + mi*16, col0 = bn + wcol + ni*16;
            #pragma unroll
            for (int j=0; j<8; j++){
                int e = lane + j*32, r = e>>4, c = e&15;
                int gr = row0 + r, gc = col0 + c;
                if (gr < M && gc < N){
                    float v = eb[r*20 + c];
                    if (bias) v += bias[gc];
                    if (EPI == 1){ v = gelu_f(v); bf16 h,l; split2(v,h,l);
                        o1[(size_t)gr*ldc+gc]=h; o2[(size_t)gr*ldc+gc]=l; }
                    else if (EPI == 2){ o0[(size_t)gr*ldc+gc] = v + res[(size_t)gr*ldres+gc]; }
                    else if (EPI == 3){
                        v += bhp[((size_t)g*S_+gr)*28 + gc/28] + bwp[((size_t)g*S_+gr)*28 + gc%28];
                        o0[(size_t)g*sC + (size_t)gr*ldc + gc] = v; }
                    else if (EPI == 4){
                        size_t o = ((size_t)(g>>4)*S_ + gr)*1024 + (size_t)(g&15)*64 + gc;
                        bf16 h,l; split2(v,h,l); o1[o]=h; o2[o]=l; }
                    else if (EPI == 5){ v += res[(size_t)gr*ldres+gc];
                        o0[(size_t)gr*ldc+gc] = v; bf16 h,l; split2(v,h,l);
                        o1[(size_t)gr*ldc+gc]=h; o2[(size_t)gr*ldc+gc]=l; }
                    else o0[(size_t)g*sC + (size_t)gr*ldc + gc] = v;
                }
            }
            __syncwarp();
        }
    }
}

__global__ void ln_k(const float* __restrict__ x, const float* __restrict__ w,
                     const float* __restrict__ bp, float* __restrict__ of,
                     bf16* __restrict__ oh, bf16* __restrict__ ol,
                     int Cw, float eps, int mode, const float* __restrict__ res)
{
    __shared__ float r1[8], r2[8], st[2];
    const int row = blockIdx.x, tid = threadIdx.x, lane = tid&31, wd = tid>>5;
    const float* xr = x + (size_t)row*Cw;
    float s=0.f, sq=0.f;
    for (int i = tid; i < Cw; i += 256){ float t = xr[i]; s += t; sq += t*t; }
    #pragma unroll
    for (int o=16;o;o>>=1){ s+=__shfl_down_sync(~0u,s,o); sq+=__shfl_down_sync(~0u,sq,o); }
    if (lane==0){ r1[wd]=s; r2[wd]=sq; }
    __syncthreads();
    if (tid==0){ float S=0,Q=0; for(int i=0;i<8;i++){S+=r1[i];Q+=r2[i];}
        float m=S/Cw, v=Q/Cw-m*m; st[0]=m; st[1]=rsqrtf(v+eps); }
    __syncthreads();
    float mean=st[0], rstd=st[1];
    for (int i = tid; i < Cw; i += 256){
        float y = (xr[i]-mean)*rstd*w[i] + bp[i];
        if (mode==2) of[(size_t)row*Cw+i] = y + res[(size_t)row*Cw+i];
        else { if (mode==1) y = gelu_f(y);
            bf16 h,l; split2(y,h,l); oh[(size_t)row*Cw+i]=h; ol[(size_t)row*Cw+i]=l; }
    }
}

__global__ void softmax_split_k(const float* __restrict__ a, bf16* __restrict__ ah, bf16* __restrict__ al)
{
    __shared__ float red[8]; __shared__ float bv;
    const size_t row = blockIdx.x;
    const float* p = a + row*S_;
    const int t = threadIdx.x, lane = t&31, wd = t>>5;
    float v[4]; float m = -1e30f;
    #pragma unroll
    for (int j=0;j<4;j++){ int i=t+j*256; v[j]=(i<S_)?p[i]:-1e30f; m=fmaxf(m,v[j]); }
    #pragma unroll
    for (int o=16;o;o>>=1) m=fmaxf(m,__shfl_xor_sync(~0u,m,o));
    if (lane==0) red[wd]=m;
    __syncthreads();
    if (t==0){ float mm=-1e30f; for(int i=0;i<8;i++) mm=fmaxf(mm,red[i]); bv=mm; }
    __syncthreads(); m=bv; __syncthreads();
    float s=0.f;
    #pragma unroll
    for (int j=0;j<4;j++){ int i=t+j*256; if(i<S_){ v[j]=__expf(v[j]-m); s+=v[j]; } }
    #pragma unroll
    for (int o=16;o;o>>=1) s+=__shfl_xor_sync(~0u,s,o);
    if (lane==0) red[wd]=s;
    __syncthreads();
    if (t==0){ float ss=0; for(int i=0;i<8;i++) ss+=red[i]; bv=1.f/ss; }
    __syncthreads();
    float inv=bv;
    #pragma unroll
    for (int j=0;j<4;j++){ int i=t+j*256; if(i<S_){ bf16 h,l; split2(v[j]*inv,h,l);
        ah[row*S_+i]=h; al[row*S_+i]=l; } }
}

__global__ void repack_k(const float* __restrict__ qkv,
    bf16* __restrict__ qh, bf16* __restrict__ ql, bf16* __restrict__ kh, bf16* __restrict__ kl,
    bf16* __restrict__ vTh, bf16* __restrict__ vTl)
{
    __shared__ float sv[32][65];
    const int g = blockIdx.y, s0 = blockIdx.x*32, b = g>>4, n = g&15, t = threadIdx.x;
    for (int e = t; e < 2048; e += 256){
        int sl = e>>6, d = e&63, s = s0+sl;
        if (s < S_){
            size_t base = ((size_t)(b*S_+s))*3072 + n*64 + d;
            float qv = qkv[base]*0.125f, kv = qkv[base+1024];
            sv[sl][d] = qkv[base+2048];
            size_t o = ((size_t)g*S_+s)*64 + d;
            bf16 h,l; split2(qv,h,l); qh[o]=h; ql[o]=l;
            split2(kv,h,l); kh[o]=h; kl[o]=l;
        }
    }
    __syncthreads();
    for (int e = t; e < 2048; e += 256){
        int d = e>>5, j = e&31, s = s0+j;
        if (s < S_){ bf16 h,l; split2(sv[j][d],h,l);
            size_t o = ((size_t)g*64+d)*S_ + s; vTh[o]=h; vTl[o]=l; }
    }
}

__global__ void relbias_k(const float* __restrict__ qkv, const float* __restrict__ rh,
                          const float* __restrict__ rw, float* __restrict__ bh, float* __restrict__ bw)
{
    const int s = blockIdx.x % S_, g = blockIdx.x / S_, b = g>>4, n = g&15;
    __shared__ float qs[64];
    const int t = threadIdx.x;
    qs[t] = qkv[((size_t)(b*S_+s))*3072 + n*64 + t];
    __syncthreads();
    const int h = s/28, w = s%28;
    if (t < 28){
        const float* r = rh + (size_t)(h-t+27)*64; float a=0.f;
        #pragma unroll
        for (int d=0;d<64;d++) a = fmaf(qs[d], r[d], a);
        bh[((size_t)g*S_+s)*28 + t] = a;
    } else if (t >= 32 && t < 60){
        const int l = t-32;
        const float* r = rw + (size_t)(w-l+27)*64; float a=0.f;
        #pragma unroll
        for (int d=0;d<64;d++) a = fmaf(qs[d], r[d], a);
        bw[((size_t)g*S_+s)*28 + l] = a;
    }
}

__global__ void wsplitT_k(const float* __restrict__ Wm, bf16* __restrict__ Th,
                          bf16* __restrict__ Tl, int K, int N)
{
    __shared__ float s[32][33];
    const int k0 = blockIdx.x*32, n0 = blockIdx.y*32, tx = threadIdx.x, ty = threadIdx.y;
    #pragma unroll
    for (int y=0;y<32;y+=8) s[ty+y][tx] = Wm[(size_t)(k0+ty+y)*N + n0+tx];
    __syncthreads();
    #pragma unroll
    for (int y=0;y<32;y+=8){
        bf16 h,l; split2(s[tx][ty+y],h,l);
        size_t o = (size_t)(n0+ty+y)*K + k0+tx; Th[o]=h; Tl[o]=l;
    }
}

constexpr int SM128 = 2*(2*128*40 + 2*128*40)*2;   // 81920 B
constexpr int SM64  = 2*(2*128*40 + 2*64*40)*2;    // 61440 B
#define GSA(p, sym) cudaGetSymbolAddress((void**)&p, sym)
extern "C" void kernel_launch(void* const* d_in, const int* in_sizes, int n_in,
                              void* d_out, int out_size)
{
    const float *x=(const float*)d_in[0], *n1w=(const float*)d_in[1], *n1b=(const float*)d_in[2],
        *qkvw=(const float*)d_in[3], *qkvb=(const float*)d_in[4], *pw=(const float*)d_in[5],
        *pb=(const float*)d_in[6], *relh=(const float*)d_in[7], *relw=(const float*)d_in[8],
        *n2w=(const float*)d_in[9], *n2b=(const float*)d_in[10], *f1w=(const float*)d_in[11],
        *f1b=(const float*)d_in[12], *f2w=(const float*)d_in[13], *f2b=(const float*)d_in[14],
        *c1w=(const float*)d_in[15], *l1w=(const float*)d_in[16], *l1b=(const float*)d_in[17],
        *c2w=(const float*)d_in[18], *l2w=(const float*)d_in[19], *l2b=(const float*)d_in[20],
        *c3w=(const float*)d_in[21], *l3w=(const float*)d_in[22], *l3b=(const float*)d_in[23];
    float* out = (float*)d_out;

    float *qkv,*bh,*bw,*attn,*x1,*x2,*c1,*c2,*c3;
    bf16 *xnh,*xnl,*qh,*ql,*kh,*kl,*vTh,*vTl,*ah,*al,*aoh,*aol,*mh,*ml,*x2h,*x2l,*c1h,*c1l,*c2h,*c2l;
    bf16 *wah,*wal,*wbh,*wbl,*wch,*wcl,*wdh,*wdl,*weh,*wel,*wfh,*wfl,*wgh,*wgl;
    GSA(qkv,g_qkv); GSA(bh,g_bh); GSA(bw,g_bw); GSA(attn,g_attn); GSA(x1,g_x1); GSA(x2,g_x2);
    GSA(c1,g_c1); GSA(c2,g_c2); GSA(c3,g_c3);
    GSA(xnh,g_xnh); GSA(xnl,g_xnl); GSA(qh,g_qh); GSA(ql,g_ql); GSA(kh,g_kh); GSA(kl,g_kl);
    GSA(vTh,g_vTh); GSA(vTl,g_vTl); GSA(ah,g_ah); GSA(al,g_al); GSA(aoh,g_aoh); GSA(aol,g_aol);
    GSA(mh,g_mh); GSA(ml,g_ml); GSA(x2h,g_x2h); GSA(x2l,g_x2l);
    GSA(c1h,g_c1h); GSA(c1l,g_c1l); GSA(c2h,g_c2h); GSA(c2l,g_c2l);
    GSA(wah,g_wah); GSA(wal,g_wal); GSA(wbh,g_wbh); GSA(wbl,g_wbl); GSA(wch,g_wch); GSA(wcl,g_wcl);
    GSA(wdh,g_wdh); GSA(wdl,g_wdl); GSA(weh,g_wel-0); GSA(weh,g_weh); GSA(wel,g_wel);
    GSA(wfh,g_wfh); GSA(wfl,g_wfl); GSA(wgh,g_wgh); GSA(wgl,g_wgl);

    cudaFuncSetAttribute(mma_gemm<128,0,0>, cudaFuncAttributeMaxDynamicSharedMemorySize, SM128);
    cudaFuncSetAttribute(mma_gemm<128,1,0>, cudaFuncAttributeMaxDynamicSharedMemorySize, SM128);
    cudaFuncSetAttribute(mma_gemm<128,2,0>, cudaFuncAttributeMaxDynamicSharedMemorySize, SM128);
    cudaFuncSetAttribute(mma_gemm<128,3,0>, cudaFuncAttributeMaxDynamicSharedMemorySize, SM128);
    cudaFuncSetAttribute(mma_gemm<128,5,0>, cudaFuncAttributeMaxDynamicSharedMemorySize, SM128);
    cudaFuncSetAttribute(mma_gemm<64,4,0>,  cudaFuncAttributeMaxDynamicSharedMemorySize, SM64);
    cudaFuncSetAttribute(mma_gemm<128,0,1>, cudaFuncAttributeMaxDynamicSharedMemorySize, SM128);

    dim3 wb(32,8);
    wsplitT_k<<<dim3(32,96), wb>>>(qkvw, wah, wal, C_, 3*C_);
    wsplitT_k<<<dim3(32,32), wb>>>(pw,  wbh, wbl, C_, C_);
    wsplitT_k<<<dim3(32,128),wb>>>(f1w, wch, wcl, C_, HID_);
    wsplitT_k<<<dim3(128,32),wb>>>(f2w, wdh, wdl, HID_, C_);
    wsplitT_k<<<dim3(32,16), wb>>>(c1w, weh, wel, C_, BC_);
    wsplitT_k<<<dim3(144,16),wb>>>(c2w, wfh, wfl, 9*BC_, BC_);
    wsplitT_k<<<dim3(16,32), wb>>>(c3w, wgh, wgl, BC_, C_);

    ln_k<<<M_,256>>>(x, n1w, n1b, nullptr, xnh, xnl, C_, 1e-5f, 0, nullptr);
    mma_gemm<128,0,0><<<dim3(49,24,1),256,SM128>>>(xnh,xnl,wah,wal, qkv,nullptr,nullptr,
        M_,3*C_,C_, C_,C_,3*C_, 0,0,0, qkvb,nullptr,0,nullptr,nullptr);
    repack_k<<<dim3(25,G_),256>>>(qkv,qh,ql,kh,kl,vTh,vTl);
    relbias_k<<<G_*S_,64>>>(qkv,relh,relw,bh,bw);
    mma_gemm<128,3,0><<<dim3(7,7,G_),256,SM128>>>(qh,ql,kh,kl, attn,nullptr,nullptr,
        S_,S_,64, 64,64,S_, (long long)S_*64,(long long)S_*64,(long long)S_*S_,
        nullptr,nullptr,0,bh,bw);
    softmax_split_k<<<G_*S_,256>>>(attn,ah,al);
    mma_gemm<64,4,0><<<dim3(7,1,G_),256,SM64>>>(ah,al,vTh,vTl, nullptr,aoh,aol,
        S_,64,S_, S_,S_,0, (long long)S_*S_,(long long)64*S_,0,
        nullptr,nullptr,0,nullptr,nullptr);
    mma_gemm<128,2,0><<<dim3(49,8,1),256,SM128>>>(aoh,aol,wbh,wbl, x1,nullptr,nullptr,
        M_,C_,C_, C_,C_,C_, 0,0,0, pb,x,C_,nullptr,nullptr);
    ln_k<<<M_,256>>>(x1, n2w, n2b, nullptr, xnh, xnl, C_, 1e-5f, 0, nullptr);
    mma_gemm<128,1,0><<<dim3(49,32,1),256,SM128>>>(xnh,xnl,wch,wcl, nullptr,mh,ml,
        M_,HID_,C_, C_,C_,HID_, 0,0,0, f1b,nullptr,0,nullptr,nullptr);
    mma_gemm<128,5,0><<<dim3(49,8,1),256,SM128>>>(mh,ml,wdh,wdl, x2,x2h,x2l,
        M_,C_,HID_, HID_,HID_,C_, 0,0,0, f2b,x1,C_,nullptr,nullptr);
    mma_gemm<128,0,0><<<dim3(49,4,1),256,SM128>>>(x2h,x2l,weh,wel, c1,nullptr,nullptr,
        M_,BC_,C_, C_,C_,BC_, 0,0,0, nullptr,nullptr,0,nullptr,nullptr);
    ln_k<<<M_,256>>>(c1, l1w, l1b, nullptr, c1h, c1l, BC_, 1e-6f, 1, nullptr);
    mma_gemm<128,0,1><<<dim3(49,4,1),256,SM128>>>(c1h,c1l,wfh,wfl, c2,nullptr,nullptr,
        M_,BC_,9*BC_, 0,9*BC_,BC_, 0,0,0, nullptr,nullptr,0,nullptr,nullptr);
    ln_k<<<M_,256>>>(c2, l2w, l2b, nullptr, c2h, c2l, BC_, 1e-6f, 1, nullptr);
    mma_gemm<128,0,0><<<dim3(49,8,1),256,SM128>>>(c2h,c2l,wgh,wgl, c3,nullptr,nullptr,
        M_,C_,BC_, BC_,BC_,C_, 0,0,0, nullptr,nullptr,0,nullptr,nullptr);
    ln_k<<<M_,256>>>(c3, l3w, l3b, out, nullptr, nullptr, C_, 1e-6f, 2, x2);
}

// round 7
// speedup vs baseline: 4.3591x; 1.2769x over previous
#include <cuda_runtime.h>
#include <cuda_fp16.h>
#include <mma.h>
#include <math.h>
#include <stdint.h>

using namespace nvcuda;
typedef __half fp16;
constexpr int C_=1024, S_=784, M_=6272, HID_=4096, BC_=512, G_=128;

__device__ __align__(16) fp16 g_xnh[M_*C_], g_xnl[M_*C_];
__device__ __align__(16) float g_qkv[M_*3*C_];
__device__ __align__(16) fp16 g_qh[G_*S_*64], g_ql[G_*S_*64], g_kh[G_*S_*64];
__device__ __align__(16) fp16 g_vTh[G_*64*S_];
__device__ __align__(16) float g_bh[G_*S_*28], g_bw[G_*S_*28];
__device__ __align__(16) float g_attn[(size_t)G_*S_*S_];
__device__ __align__(16) fp16 g_ah[(size_t)G_*S_*S_], g_al[(size_t)G_*S_*S_];
__device__ __align__(16) fp16 g_aoh[M_*C_], g_aol[M_*C_];
__device__ __align__(16) float g_x1[M_*C_];
__device__ __align__(16) fp16 g_mh[M_*HID_], g_ml[M_*HID_];
__device__ __align__(16) float g_x2[M_*C_];
__device__ __align__(16) fp16 g_x2h[M_*C_], g_x2l[M_*C_];
__device__ __align__(16) float g_c1[M_*BC_];
__device__ __align__(16) fp16 g_c1h[M_*BC_], g_c1l[M_*BC_];
__device__ __align__(16) float g_c2[M_*BC_];
__device__ __align__(16) fp16 g_c2h[M_*BC_], g_c2l[M_*BC_];
__device__ __align__(16) float g_c3[M_*C_];
__device__ __align__(16) fp16 g_wah[3*C_*C_];      // qkv^T
__device__ __align__(16) fp16 g_wbh[C_*C_];        // proj^T
__device__ __align__(16) fp16 g_wch[HID_*C_];      // fc1^T
__device__ __align__(16) fp16 g_wdh[C_*HID_];      // fc2^T
__device__ __align__(16) fp16 g_weh[BC_*C_];       // conv1^T
__device__ __align__(16) fp16 g_wfh[BC_*9*BC_];    // conv2^T
__device__ __align__(16) fp16 g_wgh[C_*BC_];       // conv3^T

__device__ __forceinline__ float gelu_f(float x){ return 0.5f*x*(1.0f+erff(x*0.7071067811865475f)); }
__device__ __forceinline__ void split2(float x, fp16&h, fp16&l){
    h = __float2half_rn(x); l = __float2half_rn(x - __half2float(h));
}

__device__ __forceinline__ void cp16(fp16* sm, const fp16* gm, bool pred){
    uint32_t sa = (uint32_t)__cvta_generic_to_shared(sm);
    int sz = pred ? 16 : 0;
    asm volatile("cp.async.ca.shared.global [%0], [%1], 16, %2;" :: "r"(sa), "l"(gm), "r"(sz));
}
#define CP_COMMIT() asm volatile("cp.async.commit_group;")

__device__ __forceinline__ void stage_tile(const fp16* __restrict__ src, int ld,
        int row0, int rmax, int k0, int K, fp16* sm, int tid, int rows){
    for (int i = tid; i < rows*4; i += 256){
        int r = i>>2, cq = i&3;
        int gr = row0 + r, gk = k0 + (cq<<3);
        bool p = (gr < rmax && gk < K);
        cp16(sm + r*40 + (cq<<3), p ? src + (size_t)gr*ld + gk : src, p);
    }
}
__device__ __forceinline__ void stage_conv(const fp16* __restrict__ src, int row0, int k0,
        fp16* sm, int tid){
    int ky = k0/1536, kxr = k0 - ky*1536, kx = kxr>>9, ci0 = kxr&511;
    for (int i = tid; i < 512; i += 256){
        int r = i>>2, cq = i&3;
        int gr = row0 + r;
        bool p = false; const fp16* g = src;
        if (gr < M_){
            int b = gr/S_, rem = gr - b*S_, h = rem/28, w = rem - h*28;
            int ih = h+ky-1, iw = w+kx-1;
            if ((unsigned)ih<28u && (unsigned)iw<28u){
                p = true; g = src + ((size_t)((b*28+ih)*28+iw))*BC_ + ci0 + (cq<<3);
            }
        }
        cp16(sm + r*40 + (cq<<3), g, p);
    }
}

// fp16x2 wmma GEMM: D = (Ah+Al)@Bh^T, 2-stage cp.async pipeline. B given as [N,K].
// EPI 0: fp32(+bias)  1: gelu->split  2: +bias+res->fp32  3: +bh+bw->fp32
// EPI 4: split scatter to [B,S,C]     5: +bias+res->fp32 AND split
template<int BN, int EPI, int GATHER>
__global__ void __launch_bounds__(256) mma_gemm(
    const fp16* __restrict__ Ah, const fp16* __restrict__ Al,
    const fp16* __restrict__ Bh,
    float* __restrict__ o0, fp16* __restrict__ o1, fp16* __restrict__ o2,
    int M, int N, int K, int lda, int ldb, int ldc,
    long long sA, long long sB, long long sC,
    const float* __restrict__ bias, const float* __restrict__ res, int ldres,
    const float* __restrict__ bhp, const float* __restrict__ bwp)
{
    constexpr int BM = 128;
    constexpr int WarpsN = (BN==128)?4:2;
    constexpr int WarpsM = 8/WarpsN;
    constexpr int WM = BM/WarpsM, WN = BN/WarpsN;
    constexpr int MI = WM/16, NI = WN/16;
    constexpr int ATILE = BM*40, BTILE = BN*40;
    constexpr int STAGE = 2*ATILE + BTILE;
    extern __shared__ __align__(128) fp16 pool[];

    const int tid = threadIdx.x, warp = tid>>5, lane = tid&31;
    const int bm = blockIdx.x*BM, bn = blockIdx.y*BN, g = blockIdx.z;
    Ah += (size_t)g*sA; Al += (size_t)g*sA; Bh += (size_t)g*sB;
    const int wrow = (warp/WarpsN)*WM, wcol = (warp%WarpsN)*WN;

    wmma::fragment<wmma::accumulator,16,16,16,float> acc[MI][NI];
    #pragma unroll
    for (int mi=0; mi<MI; mi++)
        #pragma unroll
        for (int ni=0; ni<NI; ni++) wmma::fill_fragment(acc[mi][ni], 0.f);

    const int KC = (K+31)>>5;
    auto issue = [&](int kc, int s){
        fp16* st = pool + s*STAGE;
        int k0 = kc<<5;
        if (GATHER){ stage_conv(Ah, bm, k0, st, tid); stage_conv(Al, bm, k0, st+ATILE, tid); }
        else { stage_tile(Ah, lda, bm, M, k0, K, st, tid, BM);
               stage_tile(Al, lda, bm, M, k0, K, st+ATILE, tid, BM); }
        stage_tile(Bh, ldb, bn, N, k0, K, st+2*ATILE, tid, BN);
        CP_COMMIT();
    };
    issue(0, 0);
    for (int kc = 0; kc < KC; kc++){
        int buf = kc & 1;
        if (kc+1 < KC){
            issue(kc+1, buf^1);
            asm volatile("cp.async.wait_group 1;");
        } else {
            asm volatile("cp.async.wait_group 0;");
        }
        __syncthreads();
        fp16 *Ash = pool + buf*STAGE, *Asl = Ash + ATILE, *Bsh = Ash + 2*ATILE;
        #pragma unroll
        for (int ks=0; ks<2; ks++){
            wmma::fragment<wmma::matrix_b,16,16,16,fp16,wmma::col_major> bh_f[NI];
            #pragma unroll
            for (int ni=0; ni<NI; ni++)
                wmma::load_matrix_sync(bh_f[ni], Bsh + (wcol+ni*16)*40 + ks*16, 40);
            #pragma unroll
            for (int mi=0; mi<MI; mi++){
                wmma::fragment<wmma::matrix_a,16,16,16,fp16,wmma::row_major> ah_f, al_f;
                wmma::load_matrix_sync(ah_f, Ash + (wrow+mi*16)*40 + ks*16, 40);
                wmma::load_matrix_sync(al_f, Asl + (wrow+mi*16)*40 + ks*16, 40);
                #pragma unroll
                for (int ni=0; ni<NI; ni++){
                    wmma::mma_sync(acc[mi][ni], ah_f, bh_f[ni], acc[mi][ni]);
                    wmma::mma_sync(acc[mi][ni], al_f, bh_f[ni], acc[mi][ni]);
                }
            }
        }
        __syncthreads();
    }

    float* eb = reinterpret_cast<float*>(pool) + warp*320;   // 16x20
    #pragma unroll
    for (int mi=0; mi<MI; mi++){
        #pragma unroll
        for (int ni=0; ni<NI; ni++){
            wmma::store_matrix_sync(eb, acc[mi][ni], 20, wmma::mem_row_major);
            __syncwarp();
            int row0 = bm + wrow + mi*16, col0 = bn + wcol + ni*16;
            #pragma unroll
            for (int j=0; j<8; j++){
                int e = lane + j*32, r = e>>4, c = e&15;
                int gr = row0 + r, gc = col0 + c;
                if (gr < M && gc < N){
                    float v = eb[r*20 + c];
                    if (bias) v += bias[gc];
                    if (EPI == 1){ v = gelu_f(v); fp16 h,l; split2(v,h,l);
                        o1[(size_t)gr*ldc+gc]=h; o2[(size_t)gr*ldc+gc]=l; }
                    else if (EPI == 2){ o0[(size_t)gr*ldc+gc] = v + res[(size_t)gr*ldres+gc]; }
                    else if (EPI == 3){
                        v += bhp[((size_t)g*S_+gr)*28 + gc/28] + bwp[((size_t)g*S_+gr)*28 + gc%28];
                        o0[(size_t)g*sC + (size_t)gr*ldc + gc] = v; }
                    else if (EPI == 4){
                        size_t o = ((size_t)(g>>4)*S_ + gr)*1024 + (size_t)(g&15)*64 + gc;
                        fp16 h,l; split2(v,h,l); o1[o]=h; o2[o]=l; }
                    else if (EPI == 5){ v += res[(size_t)gr*ldres+gc];
                        o0[(size_t)gr*ldc+gc] = v; fp16 h,l; split2(v,h,l);
                        o1[(size_t)gr*ldc+gc]=h; o2[(size_t)gr*ldc+gc]=l; }
                    else o0[(size_t)g*sC + (size_t)gr*ldc + gc] = v;
                }
            }
            __syncwarp();
        }
    }
}

__global__ void ln_k(const float* __restrict__ x, const float* __restrict__ w,
                     const float* __restrict__ bp, float* __restrict__ of,
                     fp16* __restrict__ oh, fp16* __restrict__ ol,
                     int Cw, float eps, int mode, const float* __restrict__ res)
{
    __shared__ float r1[8], r2[8], st[2];
    const int row = blockIdx.x, tid = threadIdx.x, lane = tid&31, wd = tid>>5;
    const float* xr = x + (size_t)row*Cw;
    float s=0.f, sq=0.f;
    for (int i = tid; i < Cw; i += 256){ float t = xr[i]; s += t; sq += t*t; }
    #pragma unroll
    for (int o=16;o;o>>=1){ s+=__shfl_down_sync(~0u,s,o); sq+=__shfl_down_sync(~0u,sq,o); }
    if (lane==0){ r1[wd]=s; r2[wd]=sq; }
    __syncthreads();
    if (tid==0){ float S=0,Q=0; for(int i=0;i<8;i++){S+=r1[i];Q+=r2[i];}
        float m=S/Cw, v=Q/Cw-m*m; st[0]=m; st[1]=rsqrtf(v+eps); }
    __syncthreads();
    float mean=st[0], rstd=st[1];
    for (int i = tid; i < Cw; i += 256){
        float y = (xr[i]-mean)*rstd*w[i] + bp[i];
        if (mode==2) of[(size_t)row*Cw+i] = y + res[(size_t)row*Cw+i];
        else { if (mode==1) y = gelu_f(y);
            fp16 h,l; split2(y,h,l); oh[(size_t)row*Cw+i]=h; ol[(size_t)row*Cw+i]=l; }
    }
}

__global__ void softmax_split_k(const float* __restrict__ a, fp16* __restrict__ ah, fp16* __restrict__ al)
{
    __shared__ float red[8]; __shared__ float bv;
    const size_t row = blockIdx.x;
    const float* p = a + row*S_;
    const int t = threadIdx.x, lane = t&31, wd = t>>5;
    float v[4]; float m = -1e30f;
    #pragma unroll
    for (int j=0;j<4;j++){ int i=t+j*256; v[j]=(i<S_)?p[i]:-1e30f; m=fmaxf(m,v[j]); }
    #pragma unroll
    for (int o=16;o;o>>=1) m=fmaxf(m,__shfl_xor_sync(~0u,m,o));
    if (lane==0) red[wd]=m;
    __syncthreads();
    if (t==0){ float mm=-1e30f; for(int i=0;i<8;i++) mm=fmaxf(mm,red[i]); bv=mm; }
    __syncthreads(); m=bv; __syncthreads();
    float s=0.f;
    #pragma unroll
    for (int j=0;j<4;j++){ int i=t+j*256; if(i<S_){ v[j]=__expf(v[j]-m); s+=v[j]; } }
    #pragma unroll
    for (int o=16;o;o>>=1) s+=__shfl_xor_sync(~0u,s,o);
    if (lane==0) red[wd]=s;
    __syncthreads();
    if (t==0){ float ss=0; for(int i=0;i<8;i++) ss+=red[i]; bv=1.f/ss; }
    __syncthreads();
    float inv=bv;
    #pragma unroll
    for (int j=0;j<4;j++){ int i=t+j*256; if(i<S_){ fp16 h,l; split2(v[j]*inv,h,l);
        ah[row*S_+i]=h; al[row*S_+i]=l; } }
}

__global__ void repack_k(const float* __restrict__ qkv,
    fp16* __restrict__ qh, fp16* __restrict__ ql, fp16* __restrict__ kh,
    fp16* __restrict__ vTh)
{
    __shared__ float sv[32][65];
    const int g = blockIdx.y, s0 = blockIdx.x*32, b = g>>4, n = g&15, t = threadIdx.x;
    for (int e = t; e < 2048; e += 256){
        int sl = e>>6, d = e&63, s = s0+sl;
        if (s < S_){
            size_t base = ((size_t)(b*S_+s))*3072 + n*64 + d;
            float qv = qkv[base]*0.125f;
            sv[sl][d] = qkv[base+2048];
            size_t o = ((size_t)g*S_+s)*64 + d;
            fp16 h,l; split2(qv,h,l); qh[o]=h; ql[o]=l;
            kh[o] = __float2half_rn(qkv[base+1024]);
        }
    }
    __syncthreads();
    for (int e = t; e < 2048; e += 256){
        int d = e>>5, j = e&31, s = s0+j;
        if (s < S_)
            vTh[((size_t)g*64+d)*S_ + s] = __float2half_rn(sv[j][d]);
    }
}

__global__ void relbias_k(const float* __restrict__ qkv, const float* __restrict__ rh,
                          const float* __restrict__ rw, float* __restrict__ bh, float* __restrict__ bw)
{
    const int s = blockIdx.x % S_, g = blockIdx.x / S_, b = g>>4, n = g&15;
    __shared__ float qs[64];
    const int t = threadIdx.x;
    qs[t] = qkv[((size_t)(b*S_+s))*3072 + n*64 + t];
    __syncthreads();
    const int h = s/28, w = s%28;
    if (t < 28){
        const float* r = rh + (size_t)(h-t+27)*64; float a=0.f;
        #pragma unroll
        for (int d=0;d<64;d++) a = fmaf(qs[d], r[d], a);
        bh[((size_t)g*S_+s)*28 + t] = a;
    } else if (t >= 32 && t < 60){
        const int l = t-32;
        const float* r = rw + (size_t)(w-l+27)*64; float a=0.f;
        #pragma unroll
        for (int d=0;d<64;d++) a = fmaf(qs[d], r[d], a);
        bw[((size_t)g*S_+s)*28 + l] = a;
    }
}

// W[K,N] -> T_hi[N,K]
__global__ void wsplitT_k(const float* __restrict__ Wm, fp16* __restrict__ Th, int K, int N)
{
    __shared__ float s[32][33];
    const int k0 = blockIdx.x*32, n0 = blockIdx.y*32, tx = threadIdx.x, ty = threadIdx.y;
    #pragma unroll
    for (int y=0;y<32;y+=8) s[ty+y][tx] = Wm[(size_t)(k0+ty+y)*N + n0+tx];
    __syncthreads();
    #pragma unroll
    for (int y=0;y<32;y+=8)
        Th[(size_t)(n0+ty+y)*K + k0+tx] = __float2half_rn(s[tx][ty+y]);
}

constexpr int SM128 = (2*128*40 + 128*40)*2*2;   // 61440 B
constexpr int SM64  = (2*128*40 + 64*40)*2*2;    // 51200 B
#define GSA(p, sym) cudaGetSymbolAddress((void**)&p, sym)
extern "C" void kernel_launch(void* const* d_in, const int* in_sizes, int n_in,
                              void* d_out, int out_size)
{
    const float *x=(const float*)d_in[0], *n1w=(const float*)d_in[1], *n1b=(const float*)d_in[2],
        *qkvw=(const float*)d_in[3], *qkvb=(const float*)d_in[4], *pw=(const float*)d_in[5],
        *pb=(const float*)d_in[6], *relh=(const float*)d_in[7], *relw=(const float*)d_in[8],
        *n2w=(const float*)d_in[9], *n2b=(const float*)d_in[10], *f1w=(const float*)d_in[11],
        *f1b=(const float*)d_in[12], *f2w=(const float*)d_in[13], *f2b=(const float*)d_in[14],
        *c1w=(const float*)d_in[15], *l1w=(const float*)d_in[16], *l1b=(const float*)d_in[17],
        *c2w=(const float*)d_in[18], *l2w=(const float*)d_in[19], *l2b=(const float*)d_in[20],
        *c3w=(const float*)d_in[21], *l3w=(const float*)d_in[22], *l3b=(const float*)d_in[23];
    float* out = (float*)d_out;

    float *qkv,*bh,*bw,*attn,*x1,*x2,*c1,*c2,*c3;
    fp16 *xnh,*xnl,*qh,*ql,*kh,*vTh,*ah,*al,*aoh,*aol,*mh,*ml,*x2h,*x2l,*c1h,*c1l,*c2h,*c2l;
    fp16 *wah,*wbh,*wch,*wdh,*weh,*wfh,*wgh;
    GSA(qkv,g_qkv); GSA(bh,g_bh); GSA(bw,g_bw); GSA(attn,g_attn); GSA(x1,g_x1); GSA(x2,g_x2);
    GSA(c1,g_c1); GSA(c2,g_c2); GSA(c3,g_c3);
    GSA(xnh,g_xnh); GSA(xnl,g_xnl); GSA(qh,g_qh); GSA(ql,g_ql); GSA(kh,g_kh);
    GSA(vTh,g_vTh); GSA(ah,g_ah); GSA(al,g_al); GSA(aoh,g_aoh); GSA(aol,g_aol);
    GSA(mh,g_mh); GSA(ml,g_ml); GSA(x2h,g_x2h); GSA(x2l,g_x2l);
    GSA(c1h,g_c1h); GSA(c1l,g_c1l); GSA(c2h,g_c2h); GSA(c2l,g_c2l);
    GSA(wah,g_wah); GSA(wbh,g_wbh); GSA(wch,g_wch); GSA(wdh,g_wdh);
    GSA(weh,g_weh); GSA(wfh,g_wfh); GSA(wgh,g_wgh);

    cudaFuncSetAttribute(mma_gemm<128,0,0>, cudaFuncAttributeMaxDynamicSharedMemorySize, SM128);
    cudaFuncSetAttribute(mma_gemm<128,1,0>, cudaFuncAttributeMaxDynamicSharedMemorySize, SM128);
    cudaFuncSetAttribute(mma_gemm<128,2,0>, cudaFuncAttributeMaxDynamicSharedMemorySize, SM128);
    cudaFuncSetAttribute(mma_gemm<128,3,0>, cudaFuncAttributeMaxDynamicSharedMemorySize, SM128);
    cudaFuncSetAttribute(mma_gemm<128,5,0>, cudaFuncAttributeMaxDynamicSharedMemorySize, SM128);
    cudaFuncSetAttribute(mma_gemm<64,4,0>,  cudaFuncAttributeMaxDynamicSharedMemorySize, SM64);
    cudaFuncSetAttribute(mma_gemm<128,0,1>, cudaFuncAttributeMaxDynamicSharedMemorySize, SM128);

    dim3 wb(32,8);
    wsplitT_k<<<dim3(32,96), wb>>>(qkvw, wah, C_, 3*C_);
    wsplitT_k<<<dim3(32,32), wb>>>(pw,  wbh, C_, C_);
    wsplitT_k<<<dim3(32,128),wb>>>(f1w, wch, C_, HID_);
    wsplitT_k<<<dim3(128,32),wb>>>(f2w, wdh, HID_, C_);
    wsplitT_k<<<dim3(32,16), wb>>>(c1w, weh, C_, BC_);
    wsplitT_k<<<dim3(144,16),wb>>>(c2w, wfh, 9*BC_, BC_);
    wsplitT_k<<<dim3(16,32), wb>>>(c3w, wgh, BC_, C_);

    ln_k<<<M_,256>>>(x, n1w, n1b, nullptr, xnh, xnl, C_, 1e-5f, 0, nullptr);
    mma_gemm<128,0,0><<<dim3(49,24,1),256,SM128>>>(xnh,xnl,wah, qkv,nullptr,nullptr,
        M_,3*C_,C_, C_,C_,3*C_, 0,0,0, qkvb,nullptr,0,nullptr,nullptr);
    repack_k<<<dim3(25,G_),256>>>(qkv,qh,ql,kh,vTh);
    relbias_k<<<G_*S_,64>>>(qkv,relh,relw,bh,bw);
    mma_gemm<128,3,0><<<dim3(7,7,G_),256,SM128>>>(qh,ql,kh, attn,nullptr,nullptr,
        S_,S_,64, 64,64,S_, (long long)S_*64,(long long)S_*64,(long long)S_*S_,
        nullptr,nullptr,0,bh,bw);
    softmax_split_k<<<G_*S_,256>>>(attn,ah,al);
    mma_gemm<64,4,0><<<dim3(7,1,G_),256,SM64>>>(ah,al,vTh, nullptr,aoh,aol,
        S_,64,S_, S_,S_,0, (long long)S_*S_,(long long)64*S_,0,
        nullptr,nullptr,0,nullptr,nullptr);
    mma_gemm<128,2,0><<<dim3(49,8,1),256,SM128>>>(aoh,aol,wbh, x1,nullptr,nullptr,
        M_,C_,C_, C_,C_,C_, 0,0,0, pb,x,C_,nullptr,nullptr);
    ln_k<<<M_,256>>>(x1, n2w, n2b, nullptr, xnh, xnl, C_, 1e-5f, 0, nullptr);
    mma_gemm<128,1,0><<<dim3(49,32,1),256,SM128>>>(xnh,xnl,wch, nullptr,mh,ml,
        M_,HID_,C_, C_,C_,HID_, 0,0,0, f1b,nullptr,0,nullptr,nullptr);
    mma_gemm<128,5,0><<<dim3(49,8,1),256,SM128>>>(mh,ml,wdh, x2,x2h,x2l,
        M_,C_,HID_, HID_,HID_,C_, 0,0,0, f2b,x1,C_,nullptr,nullptr);
    mma_gemm<128,0,0><<<dim3(49,4,1),256,SM128>>>(x2h,x2l,weh, c1,nullptr,nullptr,
        M_,BC_,C_, C_,C_,BC_, 0,0,0, nullptr,nullptr,0,nullptr,nullptr);
    ln_k<<<M_,256>>>(c1, l1w, l1b, nullptr, c1h, c1l, BC_, 1e-6f, 1, nullptr);
    mma_gemm<128,0,1><<<dim3(49,4,1),256,SM128>>>(c1h,c1l,wfh, c2,nullptr,nullptr,
        M_,BC_,9*BC_, 0,9*BC_,BC_, 0,0,0, nullptr,nullptr,0,nullptr,nullptr);
    ln_k<<<M_,256>>>(c2, l2w, l2b, nullptr, c2h, c2l, BC_, 1e-6f, 1, nullptr);
    mma_gemm<128,0,0><<<dim3(49,8,1),256,SM128>>>(c2h,c2l,wgh, c3,nullptr,nullptr,
        M_,C_,BC_, BC_,BC_,C_, 0,0,0, nullptr,nullptr,0,nullptr,nullptr);
    ln_k<<<M_,256>>>(c3, l3w, l3b, out, nullptr, nullptr, C_, 1e-6f, 2, x2);
}